// round 1
// baseline (speedup 1.0000x reference)
#include <cuda_runtime.h>
#include <cuda_bf16.h>
#include <cstdint>

// Problem constants (fixed by the dataset)
#define NN 100000
#define NE 1600000
#define F_IN 128
#define HID 64

// ---------------------------------------------------------------------------
// Scratch (allocation-free rule: __device__ globals)
// ---------------------------------------------------------------------------
__device__ float d_dinv[NN];            // degree -> d^{-1/2}
__device__ float d_g[(size_t)NN * HID]; // g = dinv * (h @ W)
__device__ float d_agg[(size_t)NN * HID];
__device__ float d_h[(size_t)NN * HID]; // inter-layer activations

// ---------------------------------------------------------------------------
// Small utility kernels
// ---------------------------------------------------------------------------
__global__ void zero_f_kernel(float* __restrict__ p, int n_float4) {
    int t = blockIdx.x * blockDim.x + threadIdx.x;
    if (t < n_float4) ((float4*)p)[t] = make_float4(0.f, 0.f, 0.f, 0.f);
}

__global__ void deg_kernel(const int* __restrict__ col, float* __restrict__ deg) {
    int e = blockIdx.x * blockDim.x + threadIdx.x;
    if (e < NE) atomicAdd(&deg[col[e]], 1.0f);
}

__global__ void dinv_kernel(float* __restrict__ dinv) {
    int i = blockIdx.x * blockDim.x + threadIdx.x;
    if (i < NN) dinv[i] = rsqrtf(dinv[i] + 1.0f);   // +1 self loop; deg>=1 always
}

// ---------------------------------------------------------------------------
// GEMM: g[i][f] = dinv[i] * sum_k h[i][k] * W[k][f]     (W: K x 64 row-major)
// Block: 256 threads -> 64 rows, 4 threads/row, each thread 16 output cols.
// W staged in shared memory.
// ---------------------------------------------------------------------------
template <int K>
__global__ void __launch_bounds__(256)
gemm_dinv_kernel(const float* __restrict__ h,
                 const float* __restrict__ W,
                 const float* __restrict__ dinv,
                 float* __restrict__ g) {
    __shared__ float Ws[K * HID];
    int tid = threadIdx.x;
    #pragma unroll 4
    for (int i = tid; i < K * HID; i += 256) Ws[i] = W[i];
    __syncthreads();

    int row = blockIdx.x * 64 + (tid >> 2);
    if (row >= NN) return;
    int fb = (tid & 3) * 16;

    float acc[16];
    #pragma unroll
    for (int j = 0; j < 16; j++) acc[j] = 0.f;

    const float4* hr = (const float4*)(h + (size_t)row * K);
    #pragma unroll 4
    for (int k4 = 0; k4 < K / 4; k4++) {
        float4 hv = hr[k4];
        const float* wsk = Ws + (k4 * 4) * HID + fb;
        #pragma unroll
        for (int j = 0; j < 16; j++) acc[j] += hv.x * wsk[j];
        wsk += HID;
        #pragma unroll
        for (int j = 0; j < 16; j++) acc[j] += hv.y * wsk[j];
        wsk += HID;
        #pragma unroll
        for (int j = 0; j < 16; j++) acc[j] += hv.z * wsk[j];
        wsk += HID;
        #pragma unroll
        for (int j = 0; j < 16; j++) acc[j] += hv.w * wsk[j];
    }

    float dv = dinv[row];
    float4* go = (float4*)(g + (size_t)row * HID + fb);
    #pragma unroll
    for (int j = 0; j < 4; j++)
        go[j] = make_float4(acc[4 * j + 0] * dv, acc[4 * j + 1] * dv,
                            acc[4 * j + 2] * dv, acc[4 * j + 3] * dv);
}

// ---------------------------------------------------------------------------
// Edge scatter: agg[col] += g[row]   (64 floats; 16 threads/edge, float4 RED)
// ---------------------------------------------------------------------------
__global__ void __launch_bounds__(256)
scatter_kernel(const int* __restrict__ rowi, const int* __restrict__ coli,
               const float* __restrict__ g, float* __restrict__ agg) {
    int t = blockIdx.x * blockDim.x + threadIdx.x;
    int e = t >> 4;
    if (e >= NE) return;
    int q = t & 15;
    int r = rowi[e];
    int c = coli[e];
    float4 v = *(const float4*)(g + (size_t)r * HID + q * 4);
    float* dst = agg + (size_t)c * HID + q * 4;
    asm volatile("red.global.add.v4.f32 [%0], {%1,%2,%3,%4};"
                 :: "l"(dst), "f"(v.x), "f"(v.y), "f"(v.z), "f"(v.w)
                 : "memory");
}

// ---------------------------------------------------------------------------
// Epilogue: out[i][f] = relu(dinv[i] * (agg[i][f] + g[i][f]) + b[f])
// (the +g term is the self loop: dinv^2 * hw)
// ---------------------------------------------------------------------------
__global__ void __launch_bounds__(256)
epilogue_kernel(const float* __restrict__ agg, const float* __restrict__ g,
                const float* __restrict__ dinv, const float* __restrict__ b,
                float* __restrict__ out) {
    int t = blockIdx.x * blockDim.x + threadIdx.x;
    int i = t >> 4;
    if (i >= NN) return;
    int q = t & 15;
    float dv = dinv[i];
    float4 a = *(const float4*)(agg + (size_t)i * HID + q * 4);
    float4 gg = *(const float4*)(g + (size_t)i * HID + q * 4);
    float4 bb = *(const float4*)(b + q * 4);
    float4 o;
    o.x = fmaxf(dv * (a.x + gg.x) + bb.x, 0.f);
    o.y = fmaxf(dv * (a.y + gg.y) + bb.y, 0.f);
    o.z = fmaxf(dv * (a.z + gg.z) + bb.z, 0.f);
    o.w = fmaxf(dv * (a.w + gg.w) + bb.w, 0.f);
    *(float4*)(out + (size_t)i * HID + q * 4) = o;
}

// ---------------------------------------------------------------------------
// Host orchestration
// ---------------------------------------------------------------------------
static void run_layer(const float* h_in, int K, const float* W, const float* b,
                      const int* rowi, const int* coli,
                      float* dinv, float* g, float* agg, float* out) {
    const int AGG_F4 = NN * HID / 4;
    zero_f_kernel<<<(AGG_F4 + 255) / 256, 256>>>(agg, AGG_F4);
    if (K == F_IN)
        gemm_dinv_kernel<F_IN><<<(NN + 63) / 64, 256>>>(h_in, W, dinv, g);
    else
        gemm_dinv_kernel<HID><<<(NN + 63) / 64, 256>>>(h_in, W, dinv, g);
    scatter_kernel<<<(NE * 16) / 256, 256>>>(rowi, coli, g, agg);
    epilogue_kernel<<<(NN * 16 + 255) / 256, 256>>>(agg, g, dinv, b, out);
}

extern "C" void kernel_launch(void* const* d_in, const int* in_sizes, int n_in,
                              void* d_out, int out_size) {
    const float* x   = (const float*)d_in[0];
    const int* eidx  = (const int*)d_in[1];   // [2, E]: first E = row, next E = col
    const float* W0  = (const float*)d_in[2];
    const float* b0  = (const float*)d_in[3];
    const float* W1  = (const float*)d_in[4];
    const float* b1  = (const float*)d_in[5];
    const float* W2  = (const float*)d_in[6];
    const float* b2  = (const float*)d_in[7];
    const float* W3  = (const float*)d_in[8];
    const float* b3  = (const float*)d_in[9];
    const float* W4  = (const float*)d_in[10];
    const float* b4  = (const float*)d_in[11];
    float* out = (float*)d_out;

    const int* rowi = eidx;
    const int* coli = eidx + NE;

    float *dinv, *g, *agg, *h;
    cudaGetSymbolAddress((void**)&dinv, d_dinv);
    cudaGetSymbolAddress((void**)&g,    d_g);
    cudaGetSymbolAddress((void**)&agg,  d_agg);
    cudaGetSymbolAddress((void**)&h,    d_h);

    // Degree -> dinv
    zero_f_kernel<<<(NN / 4 + 255) / 256, 256>>>(dinv, NN / 4);
    deg_kernel<<<(NE + 255) / 256, 256>>>(coli, dinv);
    dinv_kernel<<<(NN + 255) / 256, 256>>>(dinv);

    // 5 GCN layers (layer activations overwrite d_h in place; safe because
    // each layer's kernels are serialized on the stream and h is consumed
    // by the GEMM before the epilogue rewrites it).
    run_layer(x, F_IN, W0, b0, rowi, coli, dinv, g, agg, h);
    run_layer(h, HID,  W1, b1, rowi, coli, dinv, g, agg, h);
    run_layer(h, HID,  W2, b2, rowi, coli, dinv, g, agg, h);
    run_layer(h, HID,  W3, b3, rowi, coli, dinv, g, agg, h);
    run_layer(h, HID,  W4, b4, rowi, coli, dinv, g, agg, out);
}

// round 2
// speedup vs baseline: 1.1766x; 1.1766x over previous
#include <cuda_runtime.h>
#include <cuda_bf16.h>
#include <cstdint>

// Problem constants (fixed by the dataset)
#define NN 100000
#define NE 1600000
#define F_IN 128
#define HID 64

// ---------------------------------------------------------------------------
// Scratch (__device__ globals; allocation-free rule)
// ---------------------------------------------------------------------------
__device__ float d_dinv[NN];
__device__ int   d_hist[NN];             // in-degree histogram (col)
__device__ int   d_ptr[NN + 1];          // CSR row pointers (by col)
__device__ int   d_cursor[NN];           // fill cursors
__device__ int   d_erow[NE];             // CSR: source node per (col-sorted) edge
__device__ float d_g[(size_t)NN * HID];  // g = dinv * (h @ W)
__device__ float d_h[(size_t)NN * HID];  // inter-layer activations

// ---------------------------------------------------------------------------
// CSR build
// ---------------------------------------------------------------------------
__global__ void zero_int_kernel(int* __restrict__ p, int n) {
    int t = blockIdx.x * blockDim.x + threadIdx.x;
    if (t < n) p[t] = 0;
}

__global__ void hist_kernel(const int* __restrict__ col, int* __restrict__ hist) {
    int e = blockIdx.x * blockDim.x + threadIdx.x;
    if (e < NE) atomicAdd(&hist[col[e]], 1);
}

// Single-block exclusive scan over NN elems (1024 threads, 98-elem chunks).
// Writes ptr[0..NN] and copies to cursor.
__global__ void __launch_bounds__(1024)
scan_kernel(const int* __restrict__ hist, int* __restrict__ ptr,
            int* __restrict__ cursor) {
    __shared__ int ssum[1024];
    const int CH = (NN + 1023) / 1024;  // 98
    int t = threadIdx.x;
    int base = t * CH;
    int s = 0;
    for (int i = 0; i < CH; i++) {
        int idx = base + i;
        if (idx < NN) s += hist[idx];
    }
    ssum[t] = s;
    __syncthreads();
    // inclusive scan over 1024
    for (int off = 1; off < 1024; off <<= 1) {
        int v = (t >= off) ? ssum[t - off] : 0;
        __syncthreads();
        ssum[t] += v;
        __syncthreads();
    }
    int run = (t == 0) ? 0 : ssum[t - 1];
    if (t == 0) { ptr[0] = 0; cursor[0] = 0; }
    for (int i = 0; i < CH; i++) {
        int idx = base + i;
        if (idx < NN) {
            run += hist[idx];
            ptr[idx + 1] = run;
            if (idx + 1 < NN) cursor[idx + 1] = run;
        }
    }
}

__global__ void fill_kernel(const int* __restrict__ rowi, const int* __restrict__ coli,
                            int* __restrict__ cursor, int* __restrict__ erow) {
    int e = blockIdx.x * blockDim.x + threadIdx.x;
    if (e < NE) {
        int c = coli[e];
        int p = atomicAdd(&cursor[c], 1);
        erow[p] = rowi[e];
    }
}

__global__ void dinv_kernel(const int* __restrict__ hist, float* __restrict__ dinv) {
    int i = blockIdx.x * blockDim.x + threadIdx.x;
    if (i < NN) dinv[i] = rsqrtf((float)hist[i] + 1.0f);
}

// ---------------------------------------------------------------------------
// GEMM: g[i][f] = dinv[i] * sum_k h[i][k] * W[k][f]   (W: K x 64 row-major)
// ---------------------------------------------------------------------------
template <int K>
__global__ void __launch_bounds__(256)
gemm_dinv_kernel(const float* __restrict__ h,
                 const float* __restrict__ W,
                 const float* __restrict__ dinv,
                 float* __restrict__ g) {
    __shared__ float Ws[K * HID];
    int tid = threadIdx.x;
    #pragma unroll 4
    for (int i = tid; i < K * HID; i += 256) Ws[i] = W[i];
    __syncthreads();

    int row = blockIdx.x * 64 + (tid >> 2);
    if (row >= NN) return;
    int fb = (tid & 3) * 16;

    float acc[16];
    #pragma unroll
    for (int j = 0; j < 16; j++) acc[j] = 0.f;

    const float4* hr = (const float4*)(h + (size_t)row * K);
    #pragma unroll 4
    for (int k4 = 0; k4 < K / 4; k4++) {
        float4 hv = hr[k4];
        const float* wsk = Ws + (k4 * 4) * HID + fb;
        #pragma unroll
        for (int j = 0; j < 16; j++) acc[j] += hv.x * wsk[j];
        wsk += HID;
        #pragma unroll
        for (int j = 0; j < 16; j++) acc[j] += hv.y * wsk[j];
        wsk += HID;
        #pragma unroll
        for (int j = 0; j < 16; j++) acc[j] += hv.z * wsk[j];
        wsk += HID;
        #pragma unroll
        for (int j = 0; j < 16; j++) acc[j] += hv.w * wsk[j];
    }

    float dv = dinv[row];
    float4* go = (float4*)(g + (size_t)row * HID + fb);
    #pragma unroll
    for (int j = 0; j < 4; j++)
        go[j] = make_float4(acc[4 * j + 0] * dv, acc[4 * j + 1] * dv,
                            acc[4 * j + 2] * dv, acc[4 * j + 3] * dv);
}

// ---------------------------------------------------------------------------
// Aggregation (gather segment-sum) + fused epilogue.
// One warp per node; lane owns 2 features (float2). For each incoming edge,
// the warp reads one full 256B row of g (coalesced). Epilogue:
//   out = relu(dinv * (sum + g[self]) + b)
// ---------------------------------------------------------------------------
__global__ void __launch_bounds__(256)
aggregate_kernel(const int* __restrict__ ptr, const int* __restrict__ erow,
                 const float* __restrict__ g, const float* __restrict__ dinv,
                 const float* __restrict__ b, float* __restrict__ out) {
    int warp = (blockIdx.x * blockDim.x + threadIdx.x) >> 5;
    if (warp >= NN) return;
    int lane = threadIdx.x & 31;
    int node = warp;

    int start = ptr[node];
    int end   = ptr[node + 1];

    // self-loop term
    float2 acc = *(const float2*)(g + (size_t)node * HID + lane * 2);

    int e = start;
    // 4-way unrolled gather (independent loads -> MLP)
    for (; e + 4 <= end; e += 4) {
        int r0 = erow[e + 0];
        int r1 = erow[e + 1];
        int r2 = erow[e + 2];
        int r3 = erow[e + 3];
        float2 v0 = *(const float2*)(g + (size_t)r0 * HID + lane * 2);
        float2 v1 = *(const float2*)(g + (size_t)r1 * HID + lane * 2);
        float2 v2 = *(const float2*)(g + (size_t)r2 * HID + lane * 2);
        float2 v3 = *(const float2*)(g + (size_t)r3 * HID + lane * 2);
        acc.x += (v0.x + v1.x) + (v2.x + v3.x);
        acc.y += (v0.y + v1.y) + (v2.y + v3.y);
    }
    for (; e < end; e++) {
        int r = erow[e];
        float2 v = *(const float2*)(g + (size_t)r * HID + lane * 2);
        acc.x += v.x;
        acc.y += v.y;
    }

    float dv = dinv[node];
    float2 bb = *(const float2*)(b + lane * 2);
    float2 o;
    o.x = fmaxf(dv * acc.x + bb.x, 0.f);
    o.y = fmaxf(dv * acc.y + bb.y, 0.f);
    *(float2*)(out + (size_t)node * HID + lane * 2) = o;
}

// ---------------------------------------------------------------------------
// Host orchestration
// ---------------------------------------------------------------------------
static void run_layer(const float* h_in, int K, const float* W, const float* b,
                      const int* ptr, const int* erow,
                      float* dinv, float* g, float* out) {
    if (K == F_IN)
        gemm_dinv_kernel<F_IN><<<(NN + 63) / 64, 256>>>(h_in, W, dinv, g);
    else
        gemm_dinv_kernel<HID><<<(NN + 63) / 64, 256>>>(h_in, W, dinv, g);
    // 8 warps per block -> one node per warp
    aggregate_kernel<<<(NN + 7) / 8, 256>>>(ptr, erow, g, dinv, b, out);
}

extern "C" void kernel_launch(void* const* d_in, const int* in_sizes, int n_in,
                              void* d_out, int out_size) {
    const float* x   = (const float*)d_in[0];
    const int* eidx  = (const int*)d_in[1];   // [2, E]: first E = row, next E = col
    const float* W0  = (const float*)d_in[2];
    const float* b0  = (const float*)d_in[3];
    const float* W1  = (const float*)d_in[4];
    const float* b1  = (const float*)d_in[5];
    const float* W2  = (const float*)d_in[6];
    const float* b2  = (const float*)d_in[7];
    const float* W3  = (const float*)d_in[8];
    const float* b3  = (const float*)d_in[9];
    const float* W4  = (const float*)d_in[10];
    const float* b4  = (const float*)d_in[11];
    float* out = (float*)d_out;

    const int* rowi = eidx;
    const int* coli = eidx + NE;

    float *dinv, *g, *h;
    int *hist, *ptr, *cursor, *erow;
    cudaGetSymbolAddress((void**)&dinv,   d_dinv);
    cudaGetSymbolAddress((void**)&g,      d_g);
    cudaGetSymbolAddress((void**)&h,      d_h);
    cudaGetSymbolAddress((void**)&hist,   d_hist);
    cudaGetSymbolAddress((void**)&ptr,    d_ptr);
    cudaGetSymbolAddress((void**)&cursor, d_cursor);
    cudaGetSymbolAddress((void**)&erow,   d_erow);

    // --- Build CSR (by destination col) + dinv, once per launch ---
    zero_int_kernel<<<(NN + 255) / 256, 256>>>(hist, NN);
    hist_kernel<<<(NE + 255) / 256, 256>>>(coli, hist);
    scan_kernel<<<1, 1024>>>(hist, ptr, cursor);
    fill_kernel<<<(NE + 255) / 256, 256>>>(rowi, coli, cursor, erow);
    dinv_kernel<<<(NN + 255) / 256, 256>>>(hist, dinv);

    // --- 5 GCN layers ---
    run_layer(x, F_IN, W0, b0, ptr, erow, dinv, g, h);
    run_layer(h, HID,  W1, b1, ptr, erow, dinv, g, h);
    run_layer(h, HID,  W2, b2, ptr, erow, dinv, g, h);
    run_layer(h, HID,  W3, b3, ptr, erow, dinv, g, h);
    run_layer(h, HID,  W4, b4, ptr, erow, dinv, g, out);
}